// round 14
// baseline (speedup 1.0000x reference)
#include <cuda_runtime.h>
#include <cuda_fp16.h>
#include <cstdint>

#define L2E   1.44269504088896340736f
#define C1    (0.125f * L2E)
#define NEGA  (-1e9f * L2E)

#define TOT_ROWS (8 * 2048)

// preprocessed fp16 planes: [row][64] fp16 = 8 uint4 per row
__device__ __align__(16) uint4 g_q[TOT_ROWS * 8];
__device__ __align__(16) uint4 g_k[TOT_ROWS * 8];
__device__ __align__(16) uint4 g_v[TOT_ROWS * 8];   // mask_v folded

// smem planes (64 rows x 144 B = 9216 B each): K double, V triple buffered.
#define K0 0
#define K1 9216
#define V0 18432
// V buf j at 18432 + (j%3)*9216 ; total 46080 B
#define SMEM_PLANES 46080

__device__ __forceinline__ uint32_t smem_u32(const void* p) {
    uint32_t a;
    asm("{ .reg .u64 t; cvta.to.shared.u64 t, %1; cvt.u32.u64 %0, t; }" : "=r"(a) : "l"(p));
    return a;
}
__device__ __forceinline__ float ex2f(float x) {
    float r; asm("ex2.approx.ftz.f32 %0, %1;" : "=f"(r) : "f"(x)); return r;
}
__device__ __forceinline__ void sts128(uint32_t a, uint4 v) {
    asm volatile("st.shared.v4.b32 [%0], {%1,%2,%3,%4};"
        :: "r"(a), "r"(v.x), "r"(v.y), "r"(v.z), "r"(v.w) : "memory");
}
__device__ __forceinline__ void stsf2(uint32_t a, float x, float y) {
    asm volatile("st.shared.v2.f32 [%0], {%1,%2};" :: "r"(a), "f"(x), "f"(y) : "memory");
}
__device__ __forceinline__ float2 ldsf2(uint32_t a) {
    float2 v; asm volatile("ld.shared.v2.f32 {%0,%1}, [%2];" : "=f"(v.x), "=f"(v.y) : "r"(a));
    return v;
}
__device__ __forceinline__ uint32_t packh2(float a, float b) {
    __half2 h = __floats2half2_rn(a, b);
    return *reinterpret_cast<const uint32_t*>(&h);
}

#define LDSM_X4(r0, r1, r2, r3, addr) \
    asm volatile("ldmatrix.sync.aligned.m8n8.x4.shared.b16 {%0,%1,%2,%3}, [%4];" \
        : "=r"(r0), "=r"(r1), "=r"(r2), "=r"(r3) : "r"(addr))
#define LDSM_X4T(r0, r1, r2, r3, addr) \
    asm volatile("ldmatrix.sync.aligned.m8n8.x4.trans.shared.b16 {%0,%1,%2,%3}, [%4];" \
        : "=r"(r0), "=r"(r1), "=r"(r2), "=r"(r3) : "r"(addr))

__device__ __forceinline__ void mma16816h(float* d, const uint32_t* a, uint32_t b0, uint32_t b1) {
    asm volatile("mma.sync.aligned.m16n8k16.row.col.f32.f16.f16.f32 "
        "{%0,%1,%2,%3}, {%4,%5,%6,%7}, {%8,%9}, {%0,%1,%2,%3};"
        : "+f"(d[0]), "+f"(d[1]), "+f"(d[2]), "+f"(d[3])
        : "r"(a[0]), "r"(a[1]), "r"(a[2]), "r"(a[3]), "r"(b0), "r"(b1));
}

// ============ prep: fp16-ify Q, K, V*mv ============
__global__ void __launch_bounds__(256)
prep_kernel(const float4* __restrict__ Q, const float4* __restrict__ K,
            const float4* __restrict__ V, const float* __restrict__ MV) {
    int i = blockIdx.x * 256 + threadIdx.x;   // chunk of 8 elems
    int row = i >> 3;
    int fb = (i << 1);                        // row*16 + (i&7)*2

    float4 a, bb;
    uint4 u;
    a = Q[fb]; bb = Q[fb + 1];
    u.x = packh2(a.x, a.y); u.y = packh2(a.z, a.w);
    u.z = packh2(bb.x, bb.y); u.w = packh2(bb.z, bb.w);
    g_q[i] = u;

    a = K[fb]; bb = K[fb + 1];
    u.x = packh2(a.x, a.y); u.y = packh2(a.z, a.w);
    u.z = packh2(bb.x, bb.y); u.w = packh2(bb.z, bb.w);
    g_k[i] = u;

    float mv = MV[row];
    a = V[fb]; bb = V[fb + 1];
    u.x = packh2(a.x * mv, a.y * mv); u.y = packh2(a.z * mv, a.w * mv);
    u.z = packh2(bb.x * mv, bb.y * mv); u.w = packh2(bb.z * mv, bb.w * mv);
    g_v[i] = u;
}

// ============ attention ============
// B=8, S=2048, D=64. grid=(16,8), 256 threads = 8 warps.
// Key-split: warp = (row-group wg 0..3 [32 rows], key-half kh 0..1 [32 keys]).
// Cross-tile pipeline: iter kt does S-MMA(kt) then softmax+PV(kt-1).
__global__ void __launch_bounds__(256, 1)
attn_mma_kernel(const float* __restrict__ MQ, const float* __restrict__ MK,
                float* __restrict__ out) {
    __shared__ __align__(16) unsigned char smbuf[SMEM_PLANES];
    __shared__ float mks[3][64];
    __shared__ float lsum_sm[128];
    const uint32_t sb = smem_u32(smbuf);

    const int tid  = threadIdx.x;
    const int w    = tid >> 5;
    const int lane = tid & 31;
    const int wg   = w & 3;
    const int kh   = w >> 2;
    const int g    = lane >> 2;
    const int tq   = lane & 3;
    const int la_r = (lane & 7) + (lane & 8);
    const int la_c = (lane >> 4) << 3;
    const int lb_r = (lane & 7) + ((lane >> 4) << 3);
    const int lb_c = (lane & 8);

    const int b  = blockIdx.y;
    const int q0 = blockIdx.x * 128;
    const size_t base = (size_t)b * 2048;

    // ---- stage Q (fp16, preconverted) and load persistent fragments ----
#pragma unroll
    for (int t = 0; t < 4; t++) {
        int c = tid + 256 * t;                 // 0..1023 chunks
        int r = c >> 3, c16 = c & 7;
        sts128(sb + (uint32_t)(r * 144 + c16 * 16), g_q[(base + q0) * 8 + c]);
    }
    __syncthreads();
    uint32_t qh[2][4][4];
#pragma unroll
    for (int rf = 0; rf < 2; rf++)
#pragma unroll
        for (int kc = 0; kc < 4; kc++) {
            uint32_t off = (uint32_t)((32 * wg + 16 * rf + la_r) * 144 + (kc * 16 + la_c) * 2);
            LDSM_X4(qh[rf][kc][0], qh[rf][kc][1], qh[rf][kc][2], qh[rf][kc][3], sb + off);
        }

    float bq[2][2];
#pragma unroll
    for (int rf = 0; rf < 2; rf++) {
        bq[rf][0] = -NEGA * MQ[base + q0 + 32 * wg + 16 * rf + g];
        bq[rf][1] = -NEGA * MQ[base + q0 + 32 * wg + 16 * rf + g + 8];
    }

    float o[2][8][4];
#pragma unroll
    for (int rf = 0; rf < 2; rf++)
#pragma unroll
        for (int m = 0; m < 8; m++)
#pragma unroll
            for (int c = 0; c < 4; c++) o[rf][m][c] = 0.f;
    float lr[2][2] = {{0.f, 0.f}, {0.f, 0.f}};
    float s[2][2][4][4];                       // ping-pong x rf x n x 4

    uint4 kr[2], vr[2];
    float mk_in;

#define LDG_TILE(K0E)                                                           \
    do {                                                                        \
        const size_t cb = (base + (K0E)) * 8;                                   \
        kr[0] = g_k[cb + tid]; kr[1] = g_k[cb + tid + 256];                     \
        vr[0] = g_v[cb + tid]; vr[1] = g_v[cb + tid + 256];                     \
        mk_in = (tid < 64) ? MK[base + (K0E) + tid] : 0.f;                      \
    } while (0)

#define STS_TILE(KB, VB, SLOT)                                                  \
    do {                                                                        \
        int c0 = tid, c1 = tid + 256;                                           \
        sts128((KB) + (uint32_t)((c0 >> 3) * 144 + (c0 & 7) * 16), kr[0]);      \
        sts128((KB) + (uint32_t)((c1 >> 3) * 144 + (c1 & 7) * 16), kr[1]);      \
        sts128((VB) + (uint32_t)((c0 >> 3) * 144 + (c0 & 7) * 16), vr[0]);      \
        sts128((VB) + (uint32_t)((c1 >> 3) * 144 + (c1 & 7) * 16), vr[1]);      \
        if (tid < 64) mks[SLOT][tid] = mk_in;                                   \
    } while (0)

#define S_MMA(PB, KB)                                                           \
    do {                                                                        \
        _Pragma("unroll")                                                       \
        for (int rf = 0; rf < 2; rf++)                                          \
            _Pragma("unroll")                                                   \
            for (int n = 0; n < 4; n++)                                         \
                _Pragma("unroll")                                               \
                for (int c = 0; c < 4; c++) s[PB][rf][n][c] = 0.f;              \
        _Pragma("unroll")                                                       \
        for (int kc = 0; kc < 4; kc++) {                                        \
            _Pragma("unroll")                                                   \
            for (int npl = 0; npl < 2; npl++) {                                 \
                const int np = 2 * kh + npl;                                    \
                uint32_t off = (uint32_t)((np*16+lb_r)*144 + (kc*16+lb_c)*2);   \
                uint32_t bh0, bh1, bh2, bh3;                                    \
                LDSM_X4(bh0, bh1, bh2, bh3, (KB) + off);                        \
                mma16816h(s[PB][0][2*npl],   qh[0][kc], bh0, bh1);              \
                mma16816h(s[PB][0][2*npl+1], qh[0][kc], bh2, bh3);              \
                mma16816h(s[PB][1][2*npl],   qh[1][kc], bh0, bh1);              \
                mma16816h(s[PB][1][2*npl+1], qh[1][kc], bh2, bh3);              \
            }                                                                   \
        }                                                                       \
    } while (0)

#define SOFTPV(PB, VB, SLOT)                                                    \
    do {                                                                        \
        _Pragma("unroll")                                                       \
        for (int kcl = 0; kcl < 2; kcl++) {                                     \
            uint32_t phv[2][4];                                                 \
            _Pragma("unroll")                                                   \
            for (int rf = 0; rf < 2; rf++) {                                    \
                _Pragma("unroll")                                               \
                for (int h = 0; h < 2; h++) {                                   \
                    const int n = 2 * kcl + h;                                  \
                    int col0 = 32 * kh + 8 * n + 2 * tq;                        \
                    float mk0 = mks[SLOT][col0], mk1 = mks[SLOT][col0 + 1];     \
                    float t00 = fmaf(bq[rf][0], mk0, NEGA);                     \
                    float t01 = fmaf(bq[rf][0], mk1, NEGA);                     \
                    float t10 = fmaf(bq[rf][1], mk0, NEGA);                     \
                    float t11 = fmaf(bq[rf][1], mk1, NEGA);                     \
                    float p0 = ex2f(fmaf(s[PB][rf][n][0], C1, t00));            \
                    float p1 = ex2f(fmaf(s[PB][rf][n][1], C1, t01));            \
                    float p2 = ex2f(fmaf(s[PB][rf][n][2], C1, t10));            \
                    float p3 = ex2f(fmaf(s[PB][rf][n][3], C1, t11));            \
                    lr[rf][0] += p0 + p1;                                       \
                    lr[rf][1] += p2 + p3;                                       \
                    phv[rf][h * 2]     = packh2(p0, p1);                        \
                    phv[rf][h * 2 + 1] = packh2(p2, p3);                        \
                }                                                               \
            }                                                                   \
            const int kcg = 2 * kh + kcl;                                       \
            _Pragma("unroll")                                                   \
            for (int dp = 0; dp < 4; dp++) {                                    \
                uint32_t off = (uint32_t)((kcg*16+la_r)*144 + (dp*16+la_c)*2);  \
                uint32_t vh0, vh1, vh2, vh3;                                    \
                LDSM_X4T(vh0, vh1, vh2, vh3, (VB) + off);                       \
                mma16816h(o[0][2*dp],   phv[0], vh0, vh1);                      \
                mma16816h(o[0][2*dp+1], phv[0], vh2, vh3);                      \
                mma16816h(o[1][2*dp],   phv[1], vh0, vh1);                      \
                mma16816h(o[1][2*dp+1], phv[1], vh2, vh3);                      \
            }                                                                   \
        }                                                                       \
    } while (0)

    // ---- prologue ----
    __syncthreads();                 // Q ldmatrix reads done before K0/V0 overwrite
    LDG_TILE(0);
    STS_TILE(sb + K0, sb + V0, 0);   // tile 0 -> K buf0, V buf0
    LDG_TILE(64);                    // tile 1 in regs
    __syncthreads();

    // ---- pipelined mainloop: iter kt = S-MMA(kt) ; softmax+PV(kt-1) ----
    for (int kt = 0; kt < 32; kt++) {
        if (kt < 31) {
            const uint32_t kb = sb + ((kt + 1) & 1 ? K1 : K0);
            const uint32_t vb = sb + V0 + (uint32_t)((kt + 1) % 3) * 9216;
            STS_TILE(kb, vb, (kt + 1) % 3);
        }
        if (kt < 30) LDG_TILE((kt + 2) * 64);

        const uint32_t kcur = sb + (kt & 1 ? K1 : K0);
        const int pb = kt & 1;
        if (pb) S_MMA(1, kcur); else S_MMA(0, kcur);

        if (kt > 0) {
            const uint32_t vprev = sb + V0 + (uint32_t)((kt - 1) % 3) * 9216;
            if ((kt - 1) & 1) SOFTPV(1, vprev, (kt - 1) % 3);
            else              SOFTPV(0, vprev, (kt - 1) % 3);
        }
        __syncthreads();
    }
    // tail: softmax+PV(31)
    {
        const uint32_t vprev = sb + V0 + (uint32_t)(31 % 3) * 9216;
        SOFTPV(1, vprev, 31 % 3);
    }

    // ---- epilogue: combine key-half warp pairs ----
    __syncthreads();   // all V reads done before overlay

#pragma unroll
    for (int rf = 0; rf < 2; rf++)
#pragma unroll
        for (int j = 0; j < 2; j++) {
            lr[rf][j] += __shfl_xor_sync(0xffffffffu, lr[rf][j], 1);
            lr[rf][j] += __shfl_xor_sync(0xffffffffu, lr[rf][j], 2);
        }

    const uint32_t obase = sb + (uint32_t)wg * 8192;
    if (kh == 1) {
#pragma unroll
        for (int rf = 0; rf < 2; rf++) {
            const int rl = 16 * rf + g;
#pragma unroll
            for (int m = 0; m < 8; m++) {
                stsf2(obase + (uint32_t)((rl)     * 64 + 8 * m + 2 * tq) * 4, o[rf][m][0], o[rf][m][1]);
                stsf2(obase + (uint32_t)((rl + 8) * 64 + 8 * m + 2 * tq) * 4, o[rf][m][2], o[rf][m][3]);
            }
            if (tq == 0) {
                lsum_sm[32 * wg + 16 * rf + g]     = lr[rf][0];
                lsum_sm[32 * wg + 16 * rf + g + 8] = lr[rf][1];
            }
        }
    }
    __syncthreads();

    if (kh == 0) {
#pragma unroll
        for (int rf = 0; rf < 2; rf++) {
            const float inv0 = 1.0f / (lr[rf][0] + lsum_sm[32 * wg + 16 * rf + g]);
            const float inv1 = 1.0f / (lr[rf][1] + lsum_sm[32 * wg + 16 * rf + g + 8]);
            const int rl = 16 * rf + g;
            const size_t row0 = base + q0 + 32 * wg + rl;
            const size_t row1 = row0 + 8;
#pragma unroll
            for (int m = 0; m < 8; m++) {
                float2 a0 = ldsf2(obase + (uint32_t)((rl)     * 64 + 8 * m + 2 * tq) * 4);
                float2 a1 = ldsf2(obase + (uint32_t)((rl + 8) * 64 + 8 * m + 2 * tq) * 4);
                float2 v0 = make_float2((o[rf][m][0] + a0.x) * inv0, (o[rf][m][1] + a0.y) * inv0);
                float2 v1 = make_float2((o[rf][m][2] + a1.x) * inv1, (o[rf][m][3] + a1.y) * inv1);
                *reinterpret_cast<float2*>(out + row0 * 64 + 8 * m + 2 * tq) = v0;
                *reinterpret_cast<float2*>(out + row1 * 64 + 8 * m + 2 * tq) = v1;
            }
        }
    }
}

extern "C" void kernel_launch(void* const* d_in, const int* in_sizes, int n_in,
                              void* d_out, int out_size) {
    const float* Q  = (const float*)d_in[0];
    const float* K  = (const float*)d_in[1];
    const float* V  = (const float*)d_in[2];
    const float* MQ = (const float*)d_in[3];
    const float* MK = (const float*)d_in[4];
    const float* MV = (const float*)d_in[5];
    float* out = (float*)d_out;

    prep_kernel<<<TOT_ROWS * 8 / 256, 256>>>(
        (const float4*)Q, (const float4*)K, (const float4*)V, MV);

    dim3 grid(16, 8);
    attn_mma_kernel<<<grid, 256>>>(MQ, MK, out);
}